// round 1
// baseline (speedup 1.0000x reference)
#include <cuda_runtime.h>
#include <math.h>

// Shapes (fixed by the problem)
//   x      : [32, 512, 2048]  f32
//   w_qkv  : [6144, 2048]     f32   (out = x @ w_qkv^T)
//   w_out  : [2048, 2048]     f32
//   out    : [32, 512, 2048]  f32
static const int Bb = 32, Tt = 512, Cc = 2048, Hh = 16, Dd = 128;

// Scratch (device globals: allocation-free per harness rules)
__device__ float g_q[32L * 16 * 512 * 128];   // [B,H,T,D]
__device__ float g_k[32L * 16 * 512 * 128];
__device__ float g_v[32L * 16 * 512 * 128];
__device__ float g_y[32L * 512 * 2048];       // [B,T,C] attention output

// ---------------------------------------------------------------------------
// SGEMM: C[m,n] = sum_k A[m,k] * B[n,k]   (A: MxK row-major, B: NxK row-major)
// 128x128 tile, BK=8, 256 threads, 8x8 per thread.
// MODE 0: plain row-major store to Cout (ld = N)
// MODE 1: scatter into g_q/g_k/g_v with [B,H,T,D] layout
// ---------------------------------------------------------------------------
template <int MODE>
__global__ void __launch_bounds__(256) sgemm_kernel(
    const float* __restrict__ A, const float* __restrict__ Bm,
    float* __restrict__ Cout, int M, int N, int K)
{
    __shared__ float As[8][128];
    __shared__ float Bs[8][128];

    const int tid = threadIdx.x;
    const int tx = tid & 15;        // 0..15  (n direction)
    const int ty = tid >> 4;        // 0..15  (m direction)
    const int m0 = blockIdx.y * 128;
    const int n0 = blockIdx.x * 128;

    const int lr = tid >> 1;        // 0..127
    const int lc = (tid & 1) * 4;   // 0 or 4
    const float* Aptr = A  + (long)(m0 + lr) * K + lc;
    const float* Bptr = Bm + (long)(n0 + lr) * K + lc;

    float acc[8][8];
#pragma unroll
    for (int i = 0; i < 8; i++)
#pragma unroll
        for (int j = 0; j < 8; j++) acc[i][j] = 0.f;

    for (int k0 = 0; k0 < K; k0 += 8) {
        float4 av = *(const float4*)(Aptr + k0);
        float4 bv = *(const float4*)(Bptr + k0);
        As[lc + 0][lr] = av.x; As[lc + 1][lr] = av.y;
        As[lc + 2][lr] = av.z; As[lc + 3][lr] = av.w;
        Bs[lc + 0][lr] = bv.x; Bs[lc + 1][lr] = bv.y;
        Bs[lc + 2][lr] = bv.z; Bs[lc + 3][lr] = bv.w;
        __syncthreads();

#pragma unroll
        for (int kk = 0; kk < 8; kk++) {
            float4 a0 = *(float4*)&As[kk][ty * 8];
            float4 a1 = *(float4*)&As[kk][ty * 8 + 4];
            float4 b0 = *(float4*)&Bs[kk][tx * 8];
            float4 b1 = *(float4*)&Bs[kk][tx * 8 + 4];
            float a[8] = {a0.x, a0.y, a0.z, a0.w, a1.x, a1.y, a1.z, a1.w};
            float b[8] = {b0.x, b0.y, b0.z, b0.w, b1.x, b1.y, b1.z, b1.w};
#pragma unroll
            for (int i = 0; i < 8; i++)
#pragma unroll
                for (int j = 0; j < 8; j++)
                    acc[i][j] += a[i] * b[j];
        }
        __syncthreads();
    }

    if (MODE == 0) {
#pragma unroll
        for (int i = 0; i < 8; i++) {
            const int m = m0 + ty * 8 + i;
#pragma unroll
            for (int j = 0; j < 8; j++) {
                const int n = n0 + tx * 8 + j;
                Cout[(long)m * N + n] = acc[i][j];
            }
        }
    } else {
        // scatter into q/k/v [B,H,T,D]; within a 128-wide n tile, which/h are constant
#pragma unroll
        for (int i = 0; i < 8; i++) {
            const int m = m0 + ty * 8 + i;
            const int b = m >> 9;          // /512
            const int t = m & 511;
#pragma unroll
            for (int j = 0; j < 8; j++) {
                const int f = n0 + tx * 8 + j;
                const int which = f >> 11;            // 0,1,2
                const int rem = f & 2047;
                const int h = rem >> 7;
                const int d = rem & 127;
                float* dst = (which == 0) ? g_q : (which == 1) ? g_k : g_v;
                dst[(((b * 16 + h) * 512) + t) * 128 + d] = acc[i][j];
            }
        }
    }
}

// ---------------------------------------------------------------------------
// RoPE in-place on q and k: rotate pairs (j, j+32) of the first 64 dims.
// ---------------------------------------------------------------------------
__global__ void rope_kernel()
{
    const int per = 32 * 16 * 512 * 32;   // pairs per tensor = 8388608
    int p = blockIdx.x * blockDim.x + threadIdx.x;
    if (p >= 2 * per) return;
    float* base = (p < per) ? g_q : g_k;
    const int w = (p < per) ? p : p - per;
    const int j  = w & 31;
    const int t  = (w >> 5) & 511;
    const int bh = w >> 14;               // 0..511

    // freq_j = 10000^{-j/32}
    const float inv = expf(-(float)j * (logf(10000.f) / 32.f));
    const float ang = (float)t * inv;
    float s, c;
    sincosf(ang, &s, &c);

    const int idx = (bh * 512 + t) * 128 + j;
    const float x1 = base[idx];
    const float x2 = base[idx + 32];
    base[idx]      = x1 * c - x2 * s;
    base[idx + 32] = x2 * c + x1 * s;
}

// ---------------------------------------------------------------------------
// Flash attention: per block = (64 q-rows, one (b,h)). Loop 64-key tiles.
// Q/K/V tiles + probs staged in dynamic smem; O in registers; online softmax.
// ---------------------------------------------------------------------------
#define QSTRIDE 132
#define SSTRIDE 68
#define ATTN_SMEM_FLOATS (3 * 64 * QSTRIDE + 64 * SSTRIDE + 3 * 64)
#define ATTN_SMEM_BYTES (ATTN_SMEM_FLOATS * 4)

__global__ void __launch_bounds__(256) attn_kernel()
{
    extern __shared__ float sm[];
    float* Qs  = sm;                       // 64 x 132
    float* Ks  = Qs + 64 * QSTRIDE;        // 64 x 132
    float* Vs  = Ks + 64 * QSTRIDE;        // 64 x 132
    float* Ss  = Vs + 64 * QSTRIDE;        // 64 x 68
    float* m_i = Ss + 64 * SSTRIDE;        // 64
    float* l_i = m_i + 64;                 // 64
    float* sc  = l_i + 64;                 // 64 (rescale alpha)

    const int tid = threadIdx.x;
    const int tx = tid & 15;               // key/d direction
    const int ty = tid >> 4;               // query direction
    const int qt = blockIdx.x;             // 0..7
    const int h  = blockIdx.y;
    const int b  = blockIdx.z;
    const int bh = b * 16 + h;
    const int q0 = qt * 64;

    const float* qbase = g_q + (long)bh * 512 * 128;
    const float* kbase = g_k + (long)bh * 512 * 128;
    const float* vbase = g_v + (long)bh * 512 * 128;

    // load Q tile
#pragma unroll
    for (int u = 0; u < 8; u++) {
        const int idx = tid + u * 256;     // float4 index, 0..2047
        const int row = idx >> 5;
        const int c4  = (idx & 31) * 4;
        *(float4*)&Qs[row * QSTRIDE + c4] =
            *(const float4*)(qbase + (q0 + row) * 128 + c4);
    }
    if (tid < 64) { m_i[tid] = -INFINITY; l_i[tid] = 0.f; }

    float o[4][8];
#pragma unroll
    for (int i = 0; i < 4; i++)
#pragma unroll
        for (int j = 0; j < 8; j++) o[i][j] = 0.f;

    const float scale = 0.08838834764831845f;   // 1/sqrt(128)

    for (int kt = 0; kt <= qt; kt++) {
        __syncthreads();                   // covers Q load (iter 0) + prior Ss/Vs reads
        const int k0 = kt * 64;
#pragma unroll
        for (int u = 0; u < 8; u++) {
            const int idx = tid + u * 256;
            const int row = idx >> 5;
            const int c4  = (idx & 31) * 4;
            *(float4*)&Ks[row * QSTRIDE + c4] =
                *(const float4*)(kbase + (k0 + row) * 128 + c4);
            *(float4*)&Vs[row * QSTRIDE + c4] =
                *(const float4*)(vbase + (k0 + row) * 128 + c4);
        }
        __syncthreads();

        // S = Q K^T for this tile (each thread: 4 q-rows x 4 k-cols)
        float acc[4][4];
#pragma unroll
        for (int i = 0; i < 4; i++)
#pragma unroll
            for (int j = 0; j < 4; j++) acc[i][j] = 0.f;

        for (int d = 0; d < 128; d += 4) {
            float4 a[4], bb[4];
#pragma unroll
            for (int i = 0; i < 4; i++)
                a[i] = *(float4*)&Qs[(ty * 4 + i) * QSTRIDE + d];
#pragma unroll
            for (int j = 0; j < 4; j++)
                bb[j] = *(float4*)&Ks[(tx * 4 + j) * QSTRIDE + d];
#pragma unroll
            for (int i = 0; i < 4; i++)
#pragma unroll
                for (int j = 0; j < 4; j++) {
                    acc[i][j] += a[i].x * bb[j].x;
                    acc[i][j] += a[i].y * bb[j].y;
                    acc[i][j] += a[i].z * bb[j].z;
                    acc[i][j] += a[i].w * bb[j].w;
                }
        }

        // scale + causal mask + store to Ss
#pragma unroll
        for (int i = 0; i < 4; i++) {
            const int qr = q0 + ty * 4 + i;
#pragma unroll
            for (int j = 0; j < 4; j++) {
                const int kc = k0 + tx * 4 + j;
                Ss[(ty * 4 + i) * SSTRIDE + tx * 4 + j] =
                    (kc <= qr) ? acc[i][j] * scale : -1e30f;
            }
        }
        __syncthreads();

        // online softmax per row (one thread per row)
        if (tid < 64) {
            const int r = tid;
            const float mprev = m_i[r];
            float mx = mprev;
            for (int c = 0; c < 64; c++) mx = fmaxf(mx, Ss[r * SSTRIDE + c]);
            const float alpha = __expf(mprev - mx);
            float sum = 0.f;
            for (int c = 0; c < 64; c++) {
                const float p = __expf(Ss[r * SSTRIDE + c] - mx);
                Ss[r * SSTRIDE + c] = p;
                sum += p;
            }
            m_i[r] = mx;
            l_i[r] = l_i[r] * alpha + sum;
            sc[r] = alpha;
        }
        __syncthreads();

        // O = O*alpha + P @ V   (each thread: 4 rows x 8 d-cols)
#pragma unroll
        for (int i = 0; i < 4; i++) {
            const float al = sc[ty * 4 + i];
#pragma unroll
            for (int j = 0; j < 8; j++) o[i][j] *= al;
        }
        for (int c = 0; c < 64; c++) {
            float4 v0 = *(float4*)&Vs[c * QSTRIDE + tx * 8];
            float4 v1 = *(float4*)&Vs[c * QSTRIDE + tx * 8 + 4];
            const float vv[8] = {v0.x, v0.y, v0.z, v0.w, v1.x, v1.y, v1.z, v1.w};
#pragma unroll
            for (int i = 0; i < 4; i++) {
                const float p = Ss[(ty * 4 + i) * SSTRIDE + c];
#pragma unroll
                for (int j = 0; j < 8; j++) o[i][j] += p * vv[j];
            }
        }
    }

    // epilogue: normalize and write to g_y [B,T,C], c = h*128 + d
#pragma unroll
    for (int i = 0; i < 4; i++) {
        const int r = ty * 4 + i;
        const float inv = 1.0f / l_i[r];
        const int t = q0 + r;
        float* dst = g_y + ((long)b * 512 + t) * 2048 + h * 128 + tx * 8;
#pragma unroll
        for (int j = 0; j < 8; j++) dst[j] = o[i][j] * inv;
    }
}

// ---------------------------------------------------------------------------
extern "C" void kernel_launch(void* const* d_in, const int* in_sizes, int n_in,
                              void* d_out, int out_size)
{
    (void)in_sizes; (void)n_in; (void)out_size;
    const float* x     = (const float*)d_in[0];
    const float* w_qkv = (const float*)d_in[1];
    const float* w_out = (const float*)d_in[2];
    float* out = (float*)d_out;

    float* y_ptr = nullptr;
    cudaGetSymbolAddress((void**)&y_ptr, g_y);

    // 1) QKV projection (scatter to q/k/v)
    {
        dim3 grid(6144 / 128, 16384 / 128);   // (N tiles, M tiles)
        sgemm_kernel<1><<<grid, 256>>>(x, w_qkv, nullptr, 16384, 6144, 2048);
    }
    // 2) RoPE on q, k
    {
        const int total = 2 * 32 * 16 * 512 * 32;
        rope_kernel<<<(total + 255) / 256, 256>>>();
    }
    // 3) Attention
    {
        cudaFuncSetAttribute(attn_kernel,
                             cudaFuncAttributeMaxDynamicSharedMemorySize,
                             ATTN_SMEM_BYTES);
        dim3 grid(8, 16, 32);   // (q-tiles, H, B)
        attn_kernel<<<grid, 256, ATTN_SMEM_BYTES>>>();
    }
    // 4) Output projection
    {
        dim3 grid(2048 / 128, 16384 / 128);
        sgemm_kernel<0><<<grid, 256>>>(y_ptr, w_out, out, 16384, 2048, 2048);
    }
}

// round 3
// speedup vs baseline: 2.9621x; 2.9621x over previous
#include <cuda_runtime.h>
#include <math.h>
#include <cstdint>

// Shapes: x[32,512,2048] f32, w_qkv[6144,2048], w_out[2048,2048], out[32,512,2048]

// Scratch (device globals: allocation-free per harness rules)
__device__ float g_q[32L * 16 * 512 * 128];   // [B,H,T,D]
__device__ float g_k[32L * 16 * 512 * 128];
__device__ float g_v[32L * 16 * 512 * 128];
__device__ float g_y[32L * 512 * 2048];       // [B,T,C]

// ===========================================================================
// Helpers (sm_80-era ISA only: mma.sync tf32, ldmatrix, cp.async)
// ===========================================================================
__device__ __forceinline__ uint32_t smem_u32(const void* p) {
    uint32_t a;
    asm("{ .reg .u64 t; cvta.to.shared.u64 t, %1; cvt.u32.u64 %0, t; }" : "=r"(a) : "l"(p));
    return a;
}
__device__ __forceinline__ uint32_t swz(uint32_t off) { return off ^ ((off >> 3) & 0x70); }

#define CP_ASYNC16(dst, src) \
    asm volatile("cp.async.cg.shared.global [%0], [%1], 16;" :: "r"(dst), "l"(src))
#define CP_COMMIT() asm volatile("cp.async.commit_group;" ::: "memory")
#define CP_WAIT1() asm volatile("cp.async.wait_group 1;" ::: "memory")
#define CP_WAIT0() asm volatile("cp.async.wait_group 0;" ::: "memory")

__device__ __forceinline__ uint32_t f2tf32(uint32_t x) {
    float f = __uint_as_float(x);
    uint32_t r;
    asm("cvt.rna.tf32.f32 %0, %1;" : "=r"(r) : "f"(f));
    return r;
}

// ===========================================================================
// tf32 mma.sync GEMM: C[m,n] = sum_k A[m,k]*B[n,k]  (A: MxK, B: NxK row-major)
// 128x128x32 block tile, 8 warps (2x4), warp tile 64x32, double-buffered cp.async.
// MODE 0: row-major store. MODE 1: scatter to g_q/g_k/g_v [B,H,T,D].
// ===========================================================================
#define GEMM_SMEM_BYTES 65536   // 2 bufs x (16KB A + 16KB B)

template <int MODE>
__global__ void __launch_bounds__(256, 2) gemm_mma(
    const float* __restrict__ A, const float* __restrict__ Bm,
    float* __restrict__ Cout, int M, int N, int K)
{
    extern __shared__ char smraw[];
    const uint32_t sb = smem_u32(smraw);
    const int tid = threadIdx.x;
    const int warp = tid >> 5, lane = tid & 31;
    const int wm = warp >> 2, wn = warp & 3;
    const int m0 = blockIdx.y * 128, n0 = blockIdx.x * 128;

    float acc[4][4][4];
#pragma unroll
    for (int i = 0; i < 4; i++)
#pragma unroll
        for (int j = 0; j < 4; j++)
#pragma unroll
            for (int q = 0; q < 4; q++) acc[i][j][q] = 0.f;

    const int nch = K / 32;

    auto load_chunk = [&](int c, int buf) {
        const int k0 = c * 32;
        const uint32_t abase = sb + buf * 32768;
        const uint32_t bbase = abase + 16384;
#pragma unroll
        for (int it = 0; it < 4; it++) {
            const int t = tid + it * 256;
            const int row = t >> 3, c4 = t & 7;
            CP_ASYNC16(abase + swz((uint32_t)(row * 128 + c4 * 16)),
                       A + (size_t)(m0 + row) * K + k0 + c4 * 4);
        }
#pragma unroll
        for (int it = 0; it < 4; it++) {
            const int t = tid + it * 256;
            const int row = t >> 3, c4 = t & 7;
            CP_ASYNC16(bbase + swz((uint32_t)(row * 128 + c4 * 16)),
                       Bm + (size_t)(n0 + row) * K + k0 + c4 * 4);
        }
    };

    load_chunk(0, 0);
    CP_COMMIT();

    const int sub = lane >> 3, r8 = lane & 7;

    for (int c = 0; c < nch; c++) {
        const int buf = c & 1;
        const bool has_next = (c + 1 < nch);
        if (has_next) {
            load_chunk(c + 1, (c + 1) & 1);
            CP_COMMIT();
            CP_WAIT1();
        } else {
            CP_WAIT0();
        }
        __syncthreads();

        const uint32_t abase = sb + buf * 32768;
        const uint32_t bbase = abase + 16384;

#pragma unroll
        for (int ks = 0; ks < 4; ks++) {
            uint32_t a[4][4], b[2][4];
#pragma unroll
            for (int mf = 0; mf < 4; mf++) {
                const int row = wm * 64 + mf * 16 + (sub & 1) * 8 + r8;
                const int kb = ks * 8 + (sub >> 1) * 4;
                const uint32_t addr = abase + swz((uint32_t)(row * 128 + kb * 4));
                asm volatile("ldmatrix.sync.aligned.m8n8.x4.shared.b16 {%0,%1,%2,%3}, [%4];"
                    : "=r"(a[mf][0]), "=r"(a[mf][1]), "=r"(a[mf][2]), "=r"(a[mf][3])
                    : "r"(addr));
            }
#pragma unroll
            for (int i = 0; i < 2; i++) {
                const int row = wn * 32 + i * 16 + (sub >> 1) * 8 + r8;
                const int kb = ks * 8 + (sub & 1) * 4;
                const uint32_t addr = bbase + swz((uint32_t)(row * 128 + kb * 4));
                asm volatile("ldmatrix.sync.aligned.m8n8.x4.shared.b16 {%0,%1,%2,%3}, [%4];"
                    : "=r"(b[i][0]), "=r"(b[i][1]), "=r"(b[i][2]), "=r"(b[i][3])
                    : "r"(addr));
            }
            // round to tf32 (RNA) — symmetric error, no truncation bias
#pragma unroll
            for (int mf = 0; mf < 4; mf++)
#pragma unroll
                for (int q = 0; q < 4; q++) a[mf][q] = f2tf32(a[mf][q]);
#pragma unroll
            for (int i = 0; i < 2; i++)
#pragma unroll
                for (int q = 0; q < 4; q++) b[i][q] = f2tf32(b[i][q]);

#pragma unroll
            for (int mf = 0; mf < 4; mf++)
#pragma unroll
                for (int nf = 0; nf < 4; nf++) {
                    asm volatile(
                        "mma.sync.aligned.m16n8k8.row.col.f32.tf32.tf32.f32 "
                        "{%0,%1,%2,%3}, {%4,%5,%6,%7}, {%8,%9}, {%0,%1,%2,%3};"
                        : "+f"(acc[mf][nf][0]), "+f"(acc[mf][nf][1]),
                          "+f"(acc[mf][nf][2]), "+f"(acc[mf][nf][3])
                        : "r"(a[mf][0]), "r"(a[mf][1]), "r"(a[mf][2]), "r"(a[mf][3]),
                          "r"(b[nf >> 1][(nf & 1) * 2]), "r"(b[nf >> 1][(nf & 1) * 2 + 1]));
                }
        }
        __syncthreads();
    }

    // epilogue
    const int g = lane >> 2, tig = lane & 3;
    if (MODE == 0) {
#pragma unroll
        for (int mf = 0; mf < 4; mf++) {
            const int mA = m0 + wm * 64 + mf * 16 + g;
#pragma unroll
            for (int nf = 0; nf < 4; nf++) {
                const int nn = n0 + wn * 32 + nf * 8 + tig * 2;
                *(float2*)(Cout + (size_t)mA * N + nn) =
                    make_float2(acc[mf][nf][0], acc[mf][nf][1]);
                *(float2*)(Cout + (size_t)(mA + 8) * N + nn) =
                    make_float2(acc[mf][nf][2], acc[mf][nf][3]);
            }
        }
    } else {
        const int which = n0 >> 11;
        const int h = (n0 & 2047) >> 7;
        float* basep = (which == 0) ? g_q : (which == 1) ? g_k : g_v;
#pragma unroll
        for (int mf = 0; mf < 4; mf++) {
            const int mA = m0 + wm * 64 + mf * 16 + g;
            const int bA = mA >> 9, tA = mA & 511;
            const int mB = mA + 8;
            const int bB = mB >> 9, tB = mB & 511;
#pragma unroll
            for (int nf = 0; nf < 4; nf++) {
                const int d = wn * 32 + nf * 8 + tig * 2;
                *(float2*)(basep + ((size_t)(bA * 16 + h) * 512 + tA) * 128 + d) =
                    make_float2(acc[mf][nf][0], acc[mf][nf][1]);
                *(float2*)(basep + ((size_t)(bB * 16 + h) * 512 + tB) * 128 + d) =
                    make_float2(acc[mf][nf][2], acc[mf][nf][3]);
            }
        }
    }
}

// ---------------------------------------------------------------------------
// RoPE in-place on q and k
// ---------------------------------------------------------------------------
__global__ void rope_kernel()
{
    const int per = 32 * 16 * 512 * 32;
    int p = blockIdx.x * blockDim.x + threadIdx.x;
    if (p >= 2 * per) return;
    float* base = (p < per) ? g_q : g_k;
    const int w = (p < per) ? p : p - per;
    const int j = w & 31;
    const int t = (w >> 5) & 511;
    const int bh = w >> 14;

    const float inv = expf(-(float)j * (logf(10000.f) / 32.f));
    const float ang = (float)t * inv;
    float s, c;
    sincosf(ang, &s, &c);

    const int idx = (bh * 512 + t) * 128 + j;
    const float x1 = base[idx];
    const float x2 = base[idx + 32];
    base[idx]      = x1 * c - x2 * s;
    base[idx + 32] = x2 * c + x1 * s;
}

// ---------------------------------------------------------------------------
// Flash attention (fp32 SIMT, unchanged — known correct)
// ---------------------------------------------------------------------------
#define QSTRIDE 132
#define SSTRIDE 68
#define ATTN_SMEM_FLOATS (3 * 64 * QSTRIDE + 64 * SSTRIDE + 3 * 64)
#define ATTN_SMEM_BYTES (ATTN_SMEM_FLOATS * 4)

__global__ void __launch_bounds__(256) attn_kernel()
{
    extern __shared__ float sm[];
    float* Qs  = sm;
    float* Ks  = Qs + 64 * QSTRIDE;
    float* Vs  = Ks + 64 * QSTRIDE;
    float* Ss  = Vs + 64 * QSTRIDE;
    float* m_i = Ss + 64 * SSTRIDE;
    float* l_i = m_i + 64;
    float* sc  = l_i + 64;

    const int tid = threadIdx.x;
    const int tx = tid & 15;
    const int ty = tid >> 4;
    const int qt = blockIdx.x;
    const int h  = blockIdx.y;
    const int b  = blockIdx.z;
    const int bh = b * 16 + h;
    const int q0 = qt * 64;

    const float* qbase = g_q + (long)bh * 512 * 128;
    const float* kbase = g_k + (long)bh * 512 * 128;
    const float* vbase = g_v + (long)bh * 512 * 128;

#pragma unroll
    for (int u = 0; u < 8; u++) {
        const int idx = tid + u * 256;
        const int row = idx >> 5;
        const int c4  = (idx & 31) * 4;
        *(float4*)&Qs[row * QSTRIDE + c4] =
            *(const float4*)(qbase + (q0 + row) * 128 + c4);
    }
    if (tid < 64) { m_i[tid] = -INFINITY; l_i[tid] = 0.f; }

    float o[4][8];
#pragma unroll
    for (int i = 0; i < 4; i++)
#pragma unroll
        for (int j = 0; j < 8; j++) o[i][j] = 0.f;

    const float scale = 0.08838834764831845f;

    for (int kt = 0; kt <= qt; kt++) {
        __syncthreads();
        const int k0 = kt * 64;
#pragma unroll
        for (int u = 0; u < 8; u++) {
            const int idx = tid + u * 256;
            const int row = idx >> 5;
            const int c4  = (idx & 31) * 4;
            *(float4*)&Ks[row * QSTRIDE + c4] =
                *(const float4*)(kbase + (k0 + row) * 128 + c4);
            *(float4*)&Vs[row * QSTRIDE + c4] =
                *(const float4*)(vbase + (k0 + row) * 128 + c4);
        }
        __syncthreads();

        float acc[4][4];
#pragma unroll
        for (int i = 0; i < 4; i++)
#pragma unroll
            for (int j = 0; j < 4; j++) acc[i][j] = 0.f;

        for (int d = 0; d < 128; d += 4) {
            float4 a[4], bb[4];
#pragma unroll
            for (int i = 0; i < 4; i++)
                a[i] = *(float4*)&Qs[(ty * 4 + i) * QSTRIDE + d];
#pragma unroll
            for (int j = 0; j < 4; j++)
                bb[j] = *(float4*)&Ks[(tx * 4 + j) * QSTRIDE + d];
#pragma unroll
            for (int i = 0; i < 4; i++)
#pragma unroll
                for (int j = 0; j < 4; j++) {
                    acc[i][j] += a[i].x * bb[j].x;
                    acc[i][j] += a[i].y * bb[j].y;
                    acc[i][j] += a[i].z * bb[j].z;
                    acc[i][j] += a[i].w * bb[j].w;
                }
        }

#pragma unroll
        for (int i = 0; i < 4; i++) {
            const int qr = q0 + ty * 4 + i;
#pragma unroll
            for (int j = 0; j < 4; j++) {
                const int kc = k0 + tx * 4 + j;
                Ss[(ty * 4 + i) * SSTRIDE + tx * 4 + j] =
                    (kc <= qr) ? acc[i][j] * scale : -1e30f;
            }
        }
        __syncthreads();

        if (tid < 64) {
            const int r = tid;
            const float mprev = m_i[r];
            float mx = mprev;
            for (int c = 0; c < 64; c++) mx = fmaxf(mx, Ss[r * SSTRIDE + c]);
            const float alpha = __expf(mprev - mx);
            float sum = 0.f;
            for (int c = 0; c < 64; c++) {
                const float p = __expf(Ss[r * SSTRIDE + c] - mx);
                Ss[r * SSTRIDE + c] = p;
                sum += p;
            }
            m_i[r] = mx;
            l_i[r] = l_i[r] * alpha + sum;
            sc[r] = alpha;
        }
        __syncthreads();

#pragma unroll
        for (int i = 0; i < 4; i++) {
            const float al = sc[ty * 4 + i];
#pragma unroll
            for (int j = 0; j < 8; j++) o[i][j] *= al;
        }
        for (int c = 0; c < 64; c++) {
            float4 v0 = *(float4*)&Vs[c * QSTRIDE + tx * 8];
            float4 v1 = *(float4*)&Vs[c * QSTRIDE + tx * 8 + 4];
            const float vv[8] = {v0.x, v0.y, v0.z, v0.w, v1.x, v1.y, v1.z, v1.w};
#pragma unroll
            for (int i = 0; i < 4; i++) {
                const float p = Ss[(ty * 4 + i) * SSTRIDE + c];
#pragma unroll
                for (int j = 0; j < 8; j++) o[i][j] += p * vv[j];
            }
        }
    }

#pragma unroll
    for (int i = 0; i < 4; i++) {
        const int r = ty * 4 + i;
        const float inv = 1.0f / l_i[r];
        const int t = q0 + r;
        float* dst = g_y + ((long)b * 512 + t) * 2048 + h * 128 + tx * 8;
#pragma unroll
        for (int j = 0; j < 8; j++) dst[j] = o[i][j] * inv;
    }
}

// ---------------------------------------------------------------------------
extern "C" void kernel_launch(void* const* d_in, const int* in_sizes, int n_in,
                              void* d_out, int out_size)
{
    (void)in_sizes; (void)n_in; (void)out_size;
    const float* x     = (const float*)d_in[0];
    const float* w_qkv = (const float*)d_in[1];
    const float* w_out = (const float*)d_in[2];
    float* out = (float*)d_out;

    float* y_ptr = nullptr;
    cudaGetSymbolAddress((void**)&y_ptr, g_y);

    cudaFuncSetAttribute(gemm_mma<1>, cudaFuncAttributeMaxDynamicSharedMemorySize, GEMM_SMEM_BYTES);
    cudaFuncSetAttribute(gemm_mma<0>, cudaFuncAttributeMaxDynamicSharedMemorySize, GEMM_SMEM_BYTES);
    cudaFuncSetAttribute(attn_kernel, cudaFuncAttributeMaxDynamicSharedMemorySize, ATTN_SMEM_BYTES);

    // 1) QKV projection (tf32 mma.sync, scatter to q/k/v)
    {
        dim3 grid(6144 / 128, 16384 / 128);
        gemm_mma<1><<<grid, 256, GEMM_SMEM_BYTES>>>(x, w_qkv, nullptr, 16384, 6144, 2048);
    }
    // 2) RoPE
    {
        const int total = 2 * 32 * 16 * 512 * 32;
        rope_kernel<<<(total + 255) / 256, 256>>>();
    }
    // 3) Attention
    {
        dim3 grid(8, 16, 32);
        attn_kernel<<<grid, 256, ATTN_SMEM_BYTES>>>();
    }
    // 4) Output projection (tf32 mma.sync)
    {
        dim3 grid(2048 / 128, 16384 / 128);
        gemm_mma<0><<<grid, 256, GEMM_SMEM_BYTES>>>(y_ptr, w_out, out, 16384, 2048, 2048);
    }
}

// round 4
// speedup vs baseline: 4.7917x; 1.6177x over previous
#include <cuda_runtime.h>
#include <math.h>
#include <cstdint>

// Shapes: x[32,512,2048] f32, w_qkv[6144,2048], w_out[2048,2048], out[32,512,2048]

// Scratch (device globals: allocation-free per harness rules)
__device__ float g_q[32L * 16 * 512 * 128];   // [B,H,T,D] (fp32, pre-rope)
__device__ float g_k[32L * 16 * 512 * 128];
__device__ float g_v[32L * 16 * 512 * 128];   // tf32-rounded at gemm epilogue
__device__ float g_y[32L * 512 * 2048];       // [B,T,C] attn out (tf32-rounded)
__device__ float g_xr[32L * 512 * 2048];      // tf32-rounded x
__device__ float g_wqr[6144L * 2048];         // tf32-rounded w_qkv
__device__ float g_wor[2048L * 2048];         // tf32-rounded w_out
__device__ float g_cos[512 * 32];
__device__ float g_sin[512 * 32];

// ===========================================================================
// Helpers
// ===========================================================================
__device__ __forceinline__ uint32_t smem_u32(const void* p) {
    uint32_t a;
    asm("{ .reg .u64 t; cvta.to.shared.u64 t, %1; cvt.u32.u64 %0, t; }" : "=r"(a) : "l"(p));
    return a;
}
__device__ __forceinline__ uint32_t swz(uint32_t off) { return off ^ ((off >> 3) & 0x70); }

#define CP_ASYNC16(dst, src) \
    asm volatile("cp.async.cg.shared.global [%0], [%1], 16;" :: "r"(dst), "l"(src))
#define CP_COMMIT() asm volatile("cp.async.commit_group;" ::: "memory")
#define CP_WAIT1() asm volatile("cp.async.wait_group 1;" ::: "memory")
#define CP_WAIT0() asm volatile("cp.async.wait_group 0;" ::: "memory")

__device__ __forceinline__ float rnaf(float x) {
    uint32_t r;
    asm("cvt.rna.tf32.f32 %0, %1;" : "=r"(r) : "f"(x));
    return __uint_as_float(r);
}
__device__ __forceinline__ uint32_t U(float x) { return __float_as_uint(x); }

#define MMA_TF32(c, A0, A1, A2, A3, B0, B1) \
    asm volatile("mma.sync.aligned.m16n8k8.row.col.f32.tf32.tf32.f32 " \
        "{%0,%1,%2,%3},{%4,%5,%6,%7},{%8,%9},{%0,%1,%2,%3};" \
        : "+f"((c)[0]), "+f"((c)[1]), "+f"((c)[2]), "+f"((c)[3]) \
        : "r"(A0), "r"(A1), "r"(A2), "r"(A3), "r"(B0), "r"(B1))

// ===========================================================================
// elementwise tf32-round (RNA) kernel
// ===========================================================================
__global__ void round_tf32(const float* __restrict__ in, float* __restrict__ out, int n4)
{
    int i = blockIdx.x * blockDim.x + threadIdx.x;
    if (i >= n4) return;
    float4 v = ((const float4*)in)[i];
    v.x = rnaf(v.x); v.y = rnaf(v.y); v.z = rnaf(v.z); v.w = rnaf(v.w);
    ((float4*)out)[i] = v;
}

// rope tables (double-precision build to match numpy float64 path)
__global__ void build_tables()
{
    int i = blockIdx.x * blockDim.x + threadIdx.x;
    if (i >= 512 * 32) return;
    int t = i >> 5, j = i & 31;
    double freq = pow(10000.0, -(double)j / 32.0);
    double ang = (double)t * freq;
    g_cos[i] = (float)cos(ang);
    g_sin[i] = (float)sin(ang);
}

// ===========================================================================
// tf32 mma.sync GEMM (inputs pre-rounded to tf32): C[m,n] = sum_k A[m,k]*B[n,k]
// 128x128x32 block tile, 8 warps (2x4), warp tile 64x32, double-buffered cp.async.
// MODE 0: row-major store. MODE 1: scatter to g_q/g_k/g_v [B,H,T,D] (round v).
// ===========================================================================
#define GEMM_SMEM_BYTES 65536

template <int MODE>
__global__ void __launch_bounds__(256, 2) gemm_mma(
    const float* __restrict__ A, const float* __restrict__ Bm,
    float* __restrict__ Cout, int M, int N, int K)
{
    extern __shared__ char smraw[];
    const uint32_t sb = smem_u32(smraw);
    const int tid = threadIdx.x;
    const int warp = tid >> 5, lane = tid & 31;
    const int wm = warp >> 2, wn = warp & 3;
    const int m0 = blockIdx.y * 128, n0 = blockIdx.x * 128;

    float acc[4][4][4];
#pragma unroll
    for (int i = 0; i < 4; i++)
#pragma unroll
        for (int j = 0; j < 4; j++)
#pragma unroll
            for (int q = 0; q < 4; q++) acc[i][j][q] = 0.f;

    const int nch = K / 32;

    auto load_chunk = [&](int c, int buf) {
        const int k0 = c * 32;
        const uint32_t abase = sb + buf * 32768;
        const uint32_t bbase = abase + 16384;
#pragma unroll
        for (int it = 0; it < 4; it++) {
            const int t = tid + it * 256;
            const int row = t >> 3, c4 = t & 7;
            CP_ASYNC16(abase + swz((uint32_t)(row * 128 + c4 * 16)),
                       A + (size_t)(m0 + row) * K + k0 + c4 * 4);
        }
#pragma unroll
        for (int it = 0; it < 4; it++) {
            const int t = tid + it * 256;
            const int row = t >> 3, c4 = t & 7;
            CP_ASYNC16(bbase + swz((uint32_t)(row * 128 + c4 * 16)),
                       Bm + (size_t)(n0 + row) * K + k0 + c4 * 4);
        }
    };

    load_chunk(0, 0);
    CP_COMMIT();

    const int sub = lane >> 3, r8 = lane & 7;

    for (int c = 0; c < nch; c++) {
        const int buf = c & 1;
        const bool has_next = (c + 1 < nch);
        if (has_next) {
            load_chunk(c + 1, (c + 1) & 1);
            CP_COMMIT();
            CP_WAIT1();
        } else {
            CP_WAIT0();
        }
        __syncthreads();

        const uint32_t abase = sb + buf * 32768;
        const uint32_t bbase = abase + 16384;

#pragma unroll
        for (int ks = 0; ks < 4; ks++) {
            uint32_t a[4][4], b[2][4];
#pragma unroll
            for (int mf = 0; mf < 4; mf++) {
                const int row = wm * 64 + mf * 16 + (sub & 1) * 8 + r8;
                const int kb = ks * 8 + (sub >> 1) * 4;
                const uint32_t addr = abase + swz((uint32_t)(row * 128 + kb * 4));
                asm volatile("ldmatrix.sync.aligned.m8n8.x4.shared.b16 {%0,%1,%2,%3}, [%4];"
                    : "=r"(a[mf][0]), "=r"(a[mf][1]), "=r"(a[mf][2]), "=r"(a[mf][3])
                    : "r"(addr));
            }
#pragma unroll
            for (int i = 0; i < 2; i++) {
                const int row = wn * 32 + i * 16 + (sub >> 1) * 8 + r8;
                const int kb = ks * 8 + (sub & 1) * 4;
                const uint32_t addr = bbase + swz((uint32_t)(row * 128 + kb * 4));
                asm volatile("ldmatrix.sync.aligned.m8n8.x4.shared.b16 {%0,%1,%2,%3}, [%4];"
                    : "=r"(b[i][0]), "=r"(b[i][1]), "=r"(b[i][2]), "=r"(b[i][3])
                    : "r"(addr));
            }
#pragma unroll
            for (int mf = 0; mf < 4; mf++)
#pragma unroll
                for (int nf = 0; nf < 4; nf++) {
                    asm volatile(
                        "mma.sync.aligned.m16n8k8.row.col.f32.tf32.tf32.f32 "
                        "{%0,%1,%2,%3}, {%4,%5,%6,%7}, {%8,%9}, {%0,%1,%2,%3};"
                        : "+f"(acc[mf][nf][0]), "+f"(acc[mf][nf][1]),
                          "+f"(acc[mf][nf][2]), "+f"(acc[mf][nf][3])
                        : "r"(a[mf][0]), "r"(a[mf][1]), "r"(a[mf][2]), "r"(a[mf][3]),
                          "r"(b[nf >> 1][(nf & 1) * 2]), "r"(b[nf >> 1][(nf & 1) * 2 + 1]));
                }
        }
        __syncthreads();
    }

    // epilogue
    const int g = lane >> 2, tig = lane & 3;
    if (MODE == 0) {
#pragma unroll
        for (int mf = 0; mf < 4; mf++) {
            const int mA = m0 + wm * 64 + mf * 16 + g;
#pragma unroll
            for (int nf = 0; nf < 4; nf++) {
                const int nn = n0 + wn * 32 + nf * 8 + tig * 2;
                *(float2*)(Cout + (size_t)mA * N + nn) =
                    make_float2(acc[mf][nf][0], acc[mf][nf][1]);
                *(float2*)(Cout + (size_t)(mA + 8) * N + nn) =
                    make_float2(acc[mf][nf][2], acc[mf][nf][3]);
            }
        }
    } else {
        const int which = n0 >> 11;
        const int h = (n0 & 2047) >> 7;
        float* basep = (which == 0) ? g_q : (which == 1) ? g_k : g_v;
        const bool doround = (which == 2);   // v feeds tf32 PV mma directly
#pragma unroll
        for (int mf = 0; mf < 4; mf++) {
            const int mA = m0 + wm * 64 + mf * 16 + g;
            const int bA = mA >> 9, tA = mA & 511;
            const int mB = mA + 8;
            const int bB = mB >> 9, tB = mB & 511;
#pragma unroll
            for (int nf = 0; nf < 4; nf++) {
                const int d = wn * 32 + nf * 8 + tig * 2;
                float v0 = acc[mf][nf][0], v1 = acc[mf][nf][1];
                float v2 = acc[mf][nf][2], v3 = acc[mf][nf][3];
                if (doround) { v0 = rnaf(v0); v1 = rnaf(v1); v2 = rnaf(v2); v3 = rnaf(v3); }
                *(float2*)(basep + ((size_t)(bA * 16 + h) * 512 + tA) * 128 + d) =
                    make_float2(v0, v1);
                *(float2*)(basep + ((size_t)(bB * 16 + h) * 512 + tB) * 128 + d) =
                    make_float2(v2, v3);
            }
        }
    }
}

// ===========================================================================
// Tensor-core flash attention.
// Block = (64 q-rows, one (b,h)). 8 warps: wm 0..3 (16 q-rows), wn 0..1 (key/d half).
// QK^T: 3xTF32 (near-fp32). PV: tf32 with RNA-rounded P, V.
// RoPE folded into Q/K smem staging via g_cos/g_sin tables.
// ===========================================================================
// smem layout (float offsets)
#define AQHI 0
#define AQLO 8448
#define AKHI 16896
#define AKLO 25344
#define AVS  33792          // stride 136
#define APS  42496          // 64 x 68
#define AMI  46848
#define ALI  46912
#define AAL  46976
#define APMX 47040          // [2][64]
#define APSM 47168          // [2][64]
#define ATTN_SMEM_FLOATS 47296
#define ATTN2_SMEM_BYTES (ATTN_SMEM_FLOATS * 4)

__global__ void __launch_bounds__(256, 1) attn_mma()
{
    extern __shared__ float sm[];
    const int tid = threadIdx.x;
    const int warp = tid >> 5, lane = tid & 31;
    const int wm = warp >> 1, wn = warp & 1;
    const int g = lane >> 2, tig = lane & 3;
    const int qt = blockIdx.x, hh = blockIdx.y, bb = blockIdx.z;
    const int bh = bb * 16 + hh, q0 = qt * 64;
    const int arow = wm * 16;

    const float* qbase = g_q + (size_t)bh * 512 * 128;
    const float* kbase = g_k + (size_t)bh * 512 * 128;
    const float* vbase = g_v + (size_t)bh * 512 * 128;
    const float scale = 0.08838834764831845f;   // 1/sqrt(128)

    // ---- stage Q: rope + scale + hi/lo split ----
#pragma unroll
    for (int it = 0; it < 8; it++) {
        const int p = tid + it * 256;
        const int row = p >> 5, j = p & 31;
        const int t = q0 + row;
        const float c = g_cos[t * 32 + j], s = g_sin[t * 32 + j];
        const float x1 = qbase[(size_t)t * 128 + j];
        const float x2 = qbase[(size_t)t * 128 + j + 32];
        const float r1 = (x1 * c - x2 * s) * scale;
        const float r2 = (x2 * c + x1 * s) * scale;
        const float h1 = rnaf(r1), h2 = rnaf(r2);
        sm[AQHI + row * 132 + j] = h1;      sm[AQLO + row * 132 + j] = rnaf(r1 - h1);
        sm[AQHI + row * 132 + j + 32] = h2; sm[AQLO + row * 132 + j + 32] = rnaf(r2 - h2);
    }
#pragma unroll
    for (int it = 0; it < 16; it++) {
        const int p = tid + it * 256;
        const int row = p >> 6, d = 64 + (p & 63);
        const float v = qbase[(size_t)(q0 + row) * 128 + d] * scale;
        const float hv = rnaf(v);
        sm[AQHI + row * 132 + d] = hv;
        sm[AQLO + row * 132 + d] = rnaf(v - hv);
    }
    if (tid < 64) { sm[AMI + tid] = -1e30f; sm[ALI + tid] = 0.f; }

    float o[8][4];
#pragma unroll
    for (int i = 0; i < 8; i++)
#pragma unroll
        for (int q = 0; q < 4; q++) o[i][q] = 0.f;

    for (int kt = 0; kt <= qt; kt++) {
        const int k0 = kt * 64;
        // ---- stage K (rope + split) and V ----
#pragma unroll
        for (int it = 0; it < 8; it++) {
            const int p = tid + it * 256;
            const int row = p >> 5, j = p & 31;
            const int t = k0 + row;
            const float c = g_cos[t * 32 + j], s = g_sin[t * 32 + j];
            const float x1 = kbase[(size_t)t * 128 + j];
            const float x2 = kbase[(size_t)t * 128 + j + 32];
            const float r1 = x1 * c - x2 * s;
            const float r2 = x2 * c + x1 * s;
            const float h1 = rnaf(r1), h2 = rnaf(r2);
            sm[AKHI + row * 132 + j] = h1;      sm[AKLO + row * 132 + j] = rnaf(r1 - h1);
            sm[AKHI + row * 132 + j + 32] = h2; sm[AKLO + row * 132 + j + 32] = rnaf(r2 - h2);
        }
#pragma unroll
        for (int it = 0; it < 16; it++) {
            const int p = tid + it * 256;
            const int row = p >> 6, d = 64 + (p & 63);
            const float v = kbase[(size_t)(k0 + row) * 128 + d];
            const float hv = rnaf(v);
            sm[AKHI + row * 132 + d] = hv;
            sm[AKLO + row * 132 + d] = rnaf(v - hv);
        }
#pragma unroll
        for (int it = 0; it < 8; it++) {
            const int p = tid + it * 256;
            const int row = p >> 5, c4 = (p & 31) * 4;
            *(float4*)&sm[AVS + row * 136 + c4] =
                *(const float4*)(vbase + (size_t)(k0 + row) * 128 + c4);
        }
        __syncthreads();

        // ---- S = Q K^T (3xTF32) ----
        float sacc[4][4];
#pragma unroll
        for (int nf = 0; nf < 4; nf++)
#pragma unroll
            for (int q = 0; q < 4; q++) sacc[nf][q] = 0.f;

#pragma unroll
        for (int dc = 0; dc < 16; dc++) {
            const int d0 = dc * 8;
            const int qiA = (arow + g) * 132 + d0 + tig;
            const int qiB = (arow + g + 8) * 132 + d0 + tig;
            uint32_t ah0 = U(sm[AQHI + qiA]);
            uint32_t ah1 = U(sm[AQHI + qiB]);
            uint32_t ah2 = U(sm[AQHI + qiA + 4]);
            uint32_t ah3 = U(sm[AQHI + qiB + 4]);
            uint32_t al0 = U(sm[AQLO + qiA]);
            uint32_t al1 = U(sm[AQLO + qiB]);
            uint32_t al2 = U(sm[AQLO + qiA + 4]);
            uint32_t al3 = U(sm[AQLO + qiB + 4]);
#pragma unroll
            for (int nf = 0; nf < 4; nf++) {
                const int kr = (wn * 32 + nf * 8 + g) * 132 + d0 + tig;
                uint32_t bh0 = U(sm[AKHI + kr]);
                uint32_t bh1 = U(sm[AKHI + kr + 4]);
                uint32_t bl0 = U(sm[AKLO + kr]);
                uint32_t bl1 = U(sm[AKLO + kr + 4]);
                MMA_TF32(sacc[nf], ah0, ah1, ah2, ah3, bh0, bh1);
                MMA_TF32(sacc[nf], ah0, ah1, ah2, ah3, bl0, bl1);
                MMA_TF32(sacc[nf], al0, al1, al2, al3, bh0, bh1);
            }
        }

        // ---- causal mask (diagonal tile only) ----
        if (kt == qt) {
            const int lrA = arow + g, lrB = lrA + 8;
#pragma unroll
            for (int nf = 0; nf < 4; nf++) {
                const int lc = wn * 32 + nf * 8 + 2 * tig;
                if (lc > lrA)     sacc[nf][0] = -1e30f;
                if (lc + 1 > lrA) sacc[nf][1] = -1e30f;
                if (lc > lrB)     sacc[nf][2] = -1e30f;
                if (lc + 1 > lrB) sacc[nf][3] = -1e30f;
            }
        }

        // ---- row max ----
        float mA = -1e30f, mB = -1e30f;
#pragma unroll
        for (int nf = 0; nf < 4; nf++) {
            mA = fmaxf(mA, fmaxf(sacc[nf][0], sacc[nf][1]));
            mB = fmaxf(mB, fmaxf(sacc[nf][2], sacc[nf][3]));
        }
        mA = fmaxf(mA, __shfl_xor_sync(0xffffffffu, mA, 1));
        mA = fmaxf(mA, __shfl_xor_sync(0xffffffffu, mA, 2));
        mB = fmaxf(mB, __shfl_xor_sync(0xffffffffu, mB, 1));
        mB = fmaxf(mB, __shfl_xor_sync(0xffffffffu, mB, 2));
        if (tig == 0) {
            sm[APMX + wn * 64 + arow + g] = mA;
            sm[APMX + wn * 64 + arow + g + 8] = mB;
        }
        __syncthreads();
        if (tid < 64) {
            const float mnew = fmaxf(sm[AMI + tid],
                                     fmaxf(sm[APMX + tid], sm[APMX + 64 + tid]));
            sm[AAL + tid] = __expf(sm[AMI + tid] - mnew);
            sm[AMI + tid] = mnew;
        }
        __syncthreads();

        // ---- p = exp(s - m), write P (rounded), row sums, rescale O ----
        const float mnA = sm[AMI + arow + g], mnB = sm[AMI + arow + g + 8];
        const float alA = sm[AAL + arow + g], alB = sm[AAL + arow + g + 8];
        float sumA = 0.f, sumB = 0.f;
#pragma unroll
        for (int nf = 0; nf < 4; nf++) {
            const float p0 = __expf(sacc[nf][0] - mnA);
            const float p1 = __expf(sacc[nf][1] - mnA);
            const float p2 = __expf(sacc[nf][2] - mnB);
            const float p3 = __expf(sacc[nf][3] - mnB);
            sumA += p0 + p1; sumB += p2 + p3;
            const int col = wn * 32 + nf * 8 + 2 * tig;
            *(float2*)&sm[APS + (arow + g) * 68 + col] = make_float2(rnaf(p0), rnaf(p1));
            *(float2*)&sm[APS + (arow + g + 8) * 68 + col] = make_float2(rnaf(p2), rnaf(p3));
        }
        sumA += __shfl_xor_sync(0xffffffffu, sumA, 1);
        sumA += __shfl_xor_sync(0xffffffffu, sumA, 2);
        sumB += __shfl_xor_sync(0xffffffffu, sumB, 1);
        sumB += __shfl_xor_sync(0xffffffffu, sumB, 2);
        if (tig == 0) {
            sm[APSM + wn * 64 + arow + g] = sumA;
            sm[APSM + wn * 64 + arow + g + 8] = sumB;
        }
#pragma unroll
        for (int nf2 = 0; nf2 < 8; nf2++) {
            o[nf2][0] *= alA; o[nf2][1] *= alA;
            o[nf2][2] *= alB; o[nf2][3] *= alB;
        }
        __syncthreads();
        if (tid < 64)
            sm[ALI + tid] = sm[ALI + tid] * sm[AAL + tid]
                          + sm[APSM + tid] + sm[APSM + 64 + tid];

        // ---- O += P @ V (tf32) ----
#pragma unroll
        for (int kc = 0; kc < 8; kc++) {
            const int piA = (arow + g) * 68 + kc * 8 + tig;
            const int piB = (arow + g + 8) * 68 + kc * 8 + tig;
            uint32_t a0 = U(sm[APS + piA]);
            uint32_t a1 = U(sm[APS + piB]);
            uint32_t a2 = U(sm[APS + piA + 4]);
            uint32_t a3 = U(sm[APS + piB + 4]);
#pragma unroll
            for (int nf2 = 0; nf2 < 8; nf2++) {
                const int d = wn * 64 + nf2 * 8 + g;
                uint32_t b0 = U(sm[AVS + (kc * 8 + tig) * 136 + d]);
                uint32_t b1 = U(sm[AVS + (kc * 8 + tig + 4) * 136 + d]);
                MMA_TF32(o[nf2], a0, a1, a2, a3, b0, b1);
            }
        }
        __syncthreads();
    }

    // ---- epilogue: normalize, round to tf32 (feeds gemm2), write g_y ----
    const float invA = 1.f / sm[ALI + arow + g];
    const float invB = 1.f / sm[ALI + arow + g + 8];
    const int tA = q0 + arow + g, tB = tA + 8;
#pragma unroll
    for (int nf2 = 0; nf2 < 8; nf2++) {
        const int d = wn * 64 + nf2 * 8 + 2 * tig;
        *(float2*)(g_y + ((size_t)bb * 512 + tA) * 2048 + hh * 128 + d) =
            make_float2(rnaf(o[nf2][0] * invA), rnaf(o[nf2][1] * invA));
        *(float2*)(g_y + ((size_t)bb * 512 + tB) * 2048 + hh * 128 + d) =
            make_float2(rnaf(o[nf2][2] * invB), rnaf(o[nf2][3] * invB));
    }
}

// ---------------------------------------------------------------------------
extern "C" void kernel_launch(void* const* d_in, const int* in_sizes, int n_in,
                              void* d_out, int out_size)
{
    (void)in_sizes; (void)n_in; (void)out_size;
    const float* x     = (const float*)d_in[0];
    const float* w_qkv = (const float*)d_in[1];
    const float* w_out = (const float*)d_in[2];
    float* out = (float*)d_out;

    float *y_ptr, *xr_ptr, *wqr_ptr, *wor_ptr;
    cudaGetSymbolAddress((void**)&y_ptr, g_y);
    cudaGetSymbolAddress((void**)&xr_ptr, g_xr);
    cudaGetSymbolAddress((void**)&wqr_ptr, g_wqr);
    cudaGetSymbolAddress((void**)&wor_ptr, g_wor);

    cudaFuncSetAttribute(gemm_mma<1>, cudaFuncAttributeMaxDynamicSharedMemorySize, GEMM_SMEM_BYTES);
    cudaFuncSetAttribute(gemm_mma<0>, cudaFuncAttributeMaxDynamicSharedMemorySize, GEMM_SMEM_BYTES);
    cudaFuncSetAttribute(attn_mma, cudaFuncAttributeMaxDynamicSharedMemorySize, ATTN2_SMEM_BYTES);

    // 0) pre-round inputs to tf32 + rope tables
    round_tf32<<<(8388608 + 255) / 256, 256>>>(x, xr_ptr, 8388608);
    round_tf32<<<(3145728 + 255) / 256, 256>>>(w_qkv, wqr_ptr, 3145728);
    round_tf32<<<(1048576 + 255) / 256, 256>>>(w_out, wor_ptr, 1048576);
    build_tables<<<64, 256>>>();

    // 1) QKV projection (scatter to q/k/v; v rounded)
    {
        dim3 grid(6144 / 128, 16384 / 128);
        gemm_mma<1><<<grid, 256, GEMM_SMEM_BYTES>>>(xr_ptr, wqr_ptr, nullptr, 16384, 6144, 2048);
    }
    // 2) Attention (rope fused, tensor-core flash)
    {
        dim3 grid(8, 16, 32);
        attn_mma<<<grid, 256, ATTN2_SMEM_BYTES>>>();
    }
    // 3) Output projection
    {
        dim3 grid(2048 / 128, 16384 / 128);
        gemm_mma<0><<<grid, 256, GEMM_SMEM_BYTES>>>(y_ptr, wor_ptr, out, 16384, 2048, 2048);
    }
}